// round 12
// baseline (speedup 1.0000x reference)
#include <cuda_runtime.h>
#include <cstdint>

typedef unsigned long long ull;

#define BMAX 2048
#define NPREP 128

// ---------------- device scratch ----------------
__device__ __align__(16) float g_feat[BMAX * 450];    // SOM features [b][450]
// weights interleaved [kg][j][og][4] per-layer (OPT: 4/2/2)
__device__ __align__(16) float g_W1t[120 * 4 * 100 * 4];  // k padded 450->480
__device__ __align__(16) float g_W2t[100 * 2 * 100 * 4];
__device__ __align__(16) float g_W3t[50 * 2 * 50 * 4];
__device__ __align__(16) float g_W4t[25 * 10 * 4];        // [kg][o][4]

// ---------------- f32x2 helpers ----------------
__device__ __forceinline__ ull ffma2(ull a, ull b, ull c) {
    ull d;
    asm("fma.rn.f32x2 %0, %1, %2, %3;" : "=l"(d) : "l"(a), "l"(b), "l"(c));
    return d;
}
__device__ __forceinline__ ull addf2(ull a, ull b) {
    ull d;
    asm("add.rn.f32x2 %0, %1, %2;" : "=l"(d) : "l"(a), "l"(b));
    return d;
}
__device__ __forceinline__ ull pack2(float lo, float hi) {
    ull r;
    asm("mov.b64 %0, {%1, %2};" : "=l"(r) : "f"(lo), "f"(hi));
    return r;
}
__device__ __forceinline__ float lo32(ull v) { return __uint_as_float((unsigned)v); }
__device__ __forceinline__ float hi32(ull v) { return __uint_as_float((unsigned)(v >> 32)); }

__device__ __forceinline__ void cp_async16(uint32_t saddr, const float* g) {
    asm volatile("cp.async.cg.shared.global [%0], [%1], 16;" :: "r"(saddr), "l"(g));
}
#define CP_COMMIT() asm volatile("cp.async.commit_group;")
#define CP_WAIT0()  asm volatile("cp.async.wait_group 0;")

// ---------------- SOM + weight-prep fused; PREP BLOCKS FIRST ----------------
__global__ __launch_bounds__(256, 1) void som_kernel(const float* __restrict__ x,
                                                     const float* __restrict__ somg,
                                                     const float* __restrict__ W1, const float* __restrict__ W2,
                                                     const float* __restrict__ W3, const float* __restrict__ W4,
                                                     int B) {
    if (blockIdx.x < NPREP) {
        int i0 = blockIdx.x * 256 + threadIdx.x;
        int stride = NPREP * 256;
        for (int i = i0; i < 120 * 4 * 100 * 4; i += stride) {
            int kr = i & 3, r = i >> 2;
            int og = r % 100; r /= 100;
            int j = r & 3; int kg = r >> 2;
            int k = kg * 4 + kr, o = og * 4 + j;
            g_W1t[i] = (k < 450) ? W1[o * 450 + k] : 0.f;
        }
        for (int i = i0; i < 100 * 2 * 100 * 4; i += stride) {
            int kr = i & 3, r = i >> 2;
            int og = r % 100; r /= 100;
            int j = r & 1; int kg = r >> 1;
            g_W2t[i] = W2[(og * 2 + j) * 400 + kg * 4 + kr];
        }
        for (int i = i0; i < 50 * 2 * 50 * 4; i += stride) {
            int kr = i & 3, r = i >> 2;
            int og = r % 50; r /= 50;
            int j = r & 1; int kg = r >> 1;
            g_W3t[i] = W3[(og * 2 + j) * 200 + kg * 4 + kr];
        }
        for (int i = i0; i < 25 * 10 * 4; i += stride) {
            int kg = i / 40, r = i % 40, o = r >> 2, kr = r & 3;
            g_W4t[i] = W4[o * 100 + kg * 4 + kr];
        }
        return;
    }

    extern __shared__ float sm[];
    float* simg = sm;                          // 4 * 3072 floats
    float* spkf = sm + 12288;                  // paired codebook, 128*56 floats
    const double2* spk = (const double2*)spkf;

    int p0 = (blockIdx.x - NPREP) * 512;
    int i0 = p0 / 225;
    int total = B * 225;
#pragma unroll
    for (int s = 0; s < 4; s++) {
        int img = i0 + s; if (img > B - 1) img = B - 1;
        const float4* xb = (const float4*)(x + (size_t)img * 3072);
        float4* d = (float4*)(simg + s * 3072);
        for (int i = threadIdx.x; i < 768; i += 256) d[i] = xb[i];
    }
    {
        int c = threadIdx.x;
        int q = c >> 1, e = c & 1;
        float nrm = 0.f;
        const float* src = somg + c * 27;
#pragma unroll
        for (int k = 0; k < 27; k++) {
            float v = src[k];
            nrm += v * v;
            spkf[q * 56 + k * 2 + e] = v;
        }
        spkf[q * 56 + 54 + e] = -0.5f * nrm;
    }
    __syncthreads();

    int pA = p0 + threadIdx.x;
    int pB = pA + 256;
    bool wA = pA < total, wB = pB < total;
    if (!wA) pA = total - 1;
    if (!wB) pB = pA;

    int imgA = pA / 225, tA = pA - imgA * 225;
    int imgB = pB / 225, tB = pB - imgB * 225;
    const float* baseA = simg + (imgA - i0) * 3072 + (tA / 15) * 64 + (tA % 15) * 2;
    const float* baseB = simg + (imgB - i0) * 3072 + (tB / 15) * 64 + (tB % 15) * 2;

    ull pa[27], pb[27];
#pragma unroll
    for (int c = 0; c < 3; c++)
#pragma unroll
        for (int i = 0; i < 3; i++)
#pragma unroll
            for (int j = 0; j < 3; j++) {
                float vA = baseA[c * 1024 + i * 32 + j];
                float vB = baseB[c * 1024 + i * 32 + j];
                pa[c * 9 + i * 3 + j] = pack2(vA, vA);
                pb[c * 9 + i * 3 + j] = pack2(vB, vB);
            }

    float bestA = -3.4e38f, bestB = -3.4e38f;
    int idxA = 0, idxB = 0;
#pragma unroll 4
    for (int q = 0; q < 128; q += 2) {
        const double2* P0 = spk + q * 14;
        const double2* P1 = P0 + 14;
        double2 t0 = P0[13], t1 = P1[13];
        ull n0 = (ull)__double_as_longlong(t0.y);
        ull n1 = (ull)__double_as_longlong(t1.y);
        ull c26_0 = (ull)__double_as_longlong(t0.x);
        ull c26_1 = (ull)__double_as_longlong(t1.x);
        ull a0 = ffma2(pa[26], c26_0, n0);
        ull a1 = ffma2(pa[26], c26_1, n1);
        ull b0 = ffma2(pb[26], c26_0, n0);
        ull b1 = ffma2(pb[26], c26_1, n1);
#pragma unroll
        for (int j = 0; j < 13; j++) {
            double2 v0 = P0[j];
            double2 v1 = P1[j];
            ull w0 = (ull)__double_as_longlong(v0.x);
            ull w1 = (ull)__double_as_longlong(v0.y);
            ull w2 = (ull)__double_as_longlong(v1.x);
            ull w3 = (ull)__double_as_longlong(v1.y);
            a0 = ffma2(pa[2 * j],     w0, a0);
            b0 = ffma2(pb[2 * j],     w0, b0);
            a0 = ffma2(pa[2 * j + 1], w1, a0);
            b0 = ffma2(pb[2 * j + 1], w1, b0);
            a1 = ffma2(pa[2 * j],     w2, a1);
            b1 = ffma2(pb[2 * j],     w2, b1);
            a1 = ffma2(pa[2 * j + 1], w3, a1);
            b1 = ffma2(pb[2 * j + 1], w3, b1);
        }
        float sA0 = lo32(a0), sA1 = hi32(a0), sA2 = lo32(a1), sA3 = hi32(a1);
        if (sA0 > bestA) { bestA = sA0; idxA = 2 * q; }
        if (sA1 > bestA) { bestA = sA1; idxA = 2 * q + 1; }
        if (sA2 > bestA) { bestA = sA2; idxA = 2 * q + 2; }
        if (sA3 > bestA) { bestA = sA3; idxA = 2 * q + 3; }
        float sB0 = lo32(b0), sB1 = hi32(b0), sB2 = lo32(b1), sB3 = hi32(b1);
        if (sB0 > bestB) { bestB = sB0; idxB = 2 * q; }
        if (sB1 > bestB) { bestB = sB1; idxB = 2 * q + 1; }
        if (sB2 > bestB) { bestB = sB2; idxB = 2 * q + 2; }
        if (sB3 > bestB) { bestB = sB3; idxB = 2 * q + 3; }
    }
    if (wA) {
        float* fb = g_feat + (size_t)imgA * 450;
        fb[tA]       = (float)(idxA >> 4) * 0.0625f;
        fb[225 + tA] = (float)(idxA & 15) * 0.0625f;
    }
    if (wB) {
        float* fb = g_feat + (size_t)imgB * 450;
        fb[tB]       = (float)(idxB >> 4) * 0.0625f;
        fb[225 + tB] = (float)(idxB & 15) * 0.0625f;
    }
}

// ---------------- MLP: 512 threads, split-K halves, 14 imgs/CTA, grid 147 ----------------
// Half h processes kk = h, h+2, ... within each staged chunk (same wbuf serves both).
// Partials combined through smem with add.rn.f32x2.
#define MTHREADS 512
#define NIMG 14
#define WBUF_U2 3200                // CK=8 x 400 outs (51.2KB)

#define SA_U2 0                     // 120*14 = 1680 u2
#define SB_U2 1680                  // 100*14 = 1400 u2
#define SP_U2 3080                  // partial: 200 jobs x 28 ull = 2800 u2
#define SW_U2 5880
#define SM_U2 (5880 + 2 * WBUF_U2)  // 12280 u2 = 196.5KB

template <int NGK, int CK, int OPT, int NOG, int NOGP, int IMG, bool RELU>
__device__ __forceinline__ void layer(const float* __restrict__ Wg, const float* __restrict__ bias,
                                      const ulonglong2* sin, float* sout,
                                      ulonglong2* wbuf, uint32_t wbuf_s, ull* spart) {
    constexpr int NJG = NIMG / IMG;           // = 2
    constexpr int CEF = CK * OPT * NOG * 4;   // floats per chunk
    constexpr int NCH = NGK / CK;             // exact; CK even
    constexpr int NACC = OPT * IMG;
    int tid = threadIdx.x;

    for (int i = tid; i < CEF / 4; i += MTHREADS) cp_async16(wbuf_s + i * 16, Wg + i * 4);
    CP_COMMIT(); CP_WAIT0();
    __syncthreads();

    int half = tid >> 8;
    int t = tid & 255;
    int og = t % NOGP, jg = t / NOGP;
    bool active = (og < NOG) && (jg < NJG);
    int job = jg * NOG + og;

    ull acc[NACC];
#pragma unroll
    for (int i = 0; i < NACC; i++) acc[i] = 0;

#pragma unroll 1
    for (int c = 0; c < NCH; c++) {
        const ulonglong2* w = wbuf + (c & 1) * WBUF_U2;
        if (c + 1 < NCH) {
            uint32_t dst = wbuf_s + ((c + 1) & 1) * WBUF_U2 * 16;
            const float* src = Wg + (c + 1) * CEF;
            for (int i = tid; i < CEF / 4; i += MTHREADS) cp_async16(dst + i * 16, src + i * 4);
            CP_COMMIT();
        }
        if (active) {
#pragma unroll
            for (int kk2 = 0; kk2 < CK / 2; kk2++) {
                int kk = 2 * kk2 + half;
                ulonglong2 av[IMG], wv[OPT];
#pragma unroll
                for (int i = 0; i < IMG; i++)
                    av[i] = sin[(c * CK + kk) * NIMG + jg * IMG + i];
#pragma unroll
                for (int j = 0; j < OPT; j++)
                    wv[j] = w[(kk * OPT + j) * NOG + og];
#pragma unroll
                for (int j = 0; j < OPT; j++)
#pragma unroll
                    for (int i = 0; i < IMG; i++) {
                        acc[j * IMG + i] = ffma2(av[i].x, wv[j].x, acc[j * IMG + i]);
                        acc[j * IMG + i] = ffma2(av[i].y, wv[j].y, acc[j * IMG + i]);
                    }
            }
        }
        CP_WAIT0();
        __syncthreads();
    }

    // combine halves: half 1 stores partials, half 0 adds + finishes
    if (active && half == 1) {
#pragma unroll
        for (int i = 0; i < NACC; i++) spart[job * NACC + i] = acc[i];
    }
    __syncthreads();
    if (active && half == 0) {
        const ull* pp = spart + job * NACC;
#pragma unroll
        for (int j = 0; j < OPT; j++) {
            int o = og * OPT + j;
            float bv = __ldg(bias + o);
#pragma unroll
            for (int i = 0; i < IMG; i++) {
                ull s = addf2(acc[j * IMG + i], pp[j * IMG + i]);
                float v = lo32(s) + hi32(s) + bv;
                if (RELU) v = fmaxf(v, 0.f);
                int im = jg * IMG + i;
                sout[((o >> 2) * NIMG + im) * 4 + (o & 3)] = v;
            }
        }
    }
    __syncthreads();
}

__global__ __launch_bounds__(MTHREADS, 1) void mlp_kernel(const float* __restrict__ b1, const float* __restrict__ b2,
                                                          const float* __restrict__ b3, const float* __restrict__ b4,
                                                          float* __restrict__ out, int B) {
    extern __shared__ ulonglong2 smu[];
    ulonglong2* A = smu + SA_U2;
    ulonglong2* Bm = smu + SB_U2;
    ull* spart = (ull*)(smu + SP_U2);
    ulonglong2* wbuf = smu + SW_U2;
    uint32_t wbuf_s = (uint32_t)__cvta_generic_to_shared(wbuf);
    int tid = threadIdx.x;
    int b0 = blockIdx.x * NIMG;

    // features -> A [kg][img(14)][4], zero-pad k >= 450
    float* Af = (float*)A;
    for (int i = tid; i < 120 * NIMG * 4; i += MTHREADS) {
        int kg = i / (NIMG * 4), r = i % (NIMG * 4), im = r >> 2, kr = r & 3;
        int k = kg * 4 + kr;
        int b = b0 + im; if (b > B - 1) b = B - 1;
        Af[i] = (k < 450) ? g_feat[(size_t)b * 450 + k] : 0.f;
    }
    __syncthreads();

    layer<120, 8, 4, 100, 128, 7, true>(g_W1t, b1, A, (float*)Bm, wbuf, wbuf_s, spart);   // 450->400
    layer<100, 10, 2, 100, 128, 7, true>(g_W2t, b2, Bm, (float*)A, wbuf, wbuf_s, spart);  // 400->200
    layer<50, 10, 2, 50, 64, 7, true>(g_W3t, b3, A, (float*)Bm, wbuf, wbuf_s, spart);     // 200->100

    // final 100 -> 10 (L1-resident __ldg weights)
    for (int job = tid; job < 10 * NIMG; job += MTHREADS) {
        int o = job % 10, im = job / 10;
        const ulonglong2* ar = Bm + im;
        ull acc = 0;
#pragma unroll
        for (int kg = 0; kg < 25; kg++) {
            ulonglong2 wv = __ldg((const ulonglong2*)g_W4t + kg * 10 + o);
            ulonglong2 av = ar[kg * NIMG];
            acc = ffma2(av.x, wv.x, acc);
            acc = ffma2(av.y, wv.y, acc);
        }
        int b = b0 + im;
        if (b < B) out[(size_t)b * 10 + o] = lo32(acc) + hi32(acc) + __ldg(b4 + o);
    }
}

// ---------------- launch ----------------
extern "C" void kernel_launch(void* const* d_in, const int* in_sizes, int n_in,
                              void* d_out, int out_size) {
    const float* x   = (const float*)d_in[0];
    const float* som = (const float*)d_in[1];
    const float* W1  = (const float*)d_in[2];
    const float* b1  = (const float*)d_in[3];
    const float* W2  = (const float*)d_in[4];
    const float* b2  = (const float*)d_in[5];
    const float* W3  = (const float*)d_in[6];
    const float* b3  = (const float*)d_in[7];
    const float* W4  = (const float*)d_in[8];
    const float* b4  = (const float*)d_in[9];
    float* out = (float*)d_out;

    int B = in_sizes[0] / 3072;
    if (B > BMAX) B = BMAX;

    int som_smem = (4 * 3072) * 4 + 128 * 56 * 4;   // 77824 B
    cudaFuncSetAttribute(som_kernel, cudaFuncAttributeMaxDynamicSharedMemorySize, som_smem);
    cudaFuncSetAttribute(mlp_kernel, cudaFuncAttributeMaxDynamicSharedMemorySize, SM_U2 * 16);

    int total_p = B * 225;
    int nsom = (total_p + 511) / 512;
    som_kernel<<<NPREP + nsom, 256, som_smem>>>(x, som, W1, W2, W3, W4, B);
    mlp_kernel<<<(B + NIMG - 1) / NIMG, MTHREADS, SM_U2 * 16>>>(b1, b2, b3, b4, out, B);
}

// round 13
// speedup vs baseline: 1.0994x; 1.0994x over previous
#include <cuda_runtime.h>
#include <cstdint>

typedef unsigned long long ull;

#define BMAX 2048
#define NPREP 128

// ---------------- device scratch ----------------
__device__ __align__(16) float g_feat[BMAX * 450];    // SOM features [b][450]
// weights interleaved [kg][j][og][4] per-layer (OPT: 4/2/2)
__device__ __align__(16) float g_W1t[120 * 4 * 100 * 4];  // k padded 450->480
__device__ __align__(16) float g_W2t[100 * 2 * 100 * 4];
__device__ __align__(16) float g_W3t[50 * 2 * 50 * 4];
__device__ __align__(16) float g_W4t[25 * 10 * 4];        // [kg][o][4]

// ---------------- f32x2 helpers ----------------
__device__ __forceinline__ ull ffma2(ull a, ull b, ull c) {
    ull d;
    asm("fma.rn.f32x2 %0, %1, %2, %3;" : "=l"(d) : "l"(a), "l"(b), "l"(c));
    return d;
}
__device__ __forceinline__ ull pack2(float lo, float hi) {
    ull r;
    asm("mov.b64 %0, {%1, %2};" : "=l"(r) : "f"(lo), "f"(hi));
    return r;
}
__device__ __forceinline__ float lo32(ull v) { return __uint_as_float((unsigned)v); }
__device__ __forceinline__ float hi32(ull v) { return __uint_as_float((unsigned)(v >> 32)); }

__device__ __forceinline__ void cp_async16(uint32_t saddr, const float* g) {
    asm volatile("cp.async.cg.shared.global [%0], [%1], 16;" :: "r"(saddr), "l"(g));
}
#define CP_COMMIT() asm volatile("cp.async.commit_group;")
#define CP_WAIT0()  asm volatile("cp.async.wait_group 0;")

// ---------------- SOM + weight-prep fused; PREP BLOCKS FIRST ----------------
// Blocks [0, NPREP): weight interleave (wave 1, concurrent with som).
// Blocks [NPREP, NPREP+nsom): SOM, 768 patches/CTA, 3 patches/thread.
__global__ __launch_bounds__(256, 1) void som_kernel(const float* __restrict__ x,
                                                     const float* __restrict__ somg,
                                                     const float* __restrict__ W1, const float* __restrict__ W2,
                                                     const float* __restrict__ W3, const float* __restrict__ W4,
                                                     int B) {
    if (blockIdx.x < NPREP) {
        int i0 = blockIdx.x * 256 + threadIdx.x;
        int stride = NPREP * 256;
        for (int i = i0; i < 120 * 4 * 100 * 4; i += stride) {
            int kr = i & 3, r = i >> 2;
            int og = r % 100; r /= 100;
            int j = r & 3; int kg = r >> 2;
            int k = kg * 4 + kr, o = og * 4 + j;
            g_W1t[i] = (k < 450) ? W1[o * 450 + k] : 0.f;
        }
        for (int i = i0; i < 100 * 2 * 100 * 4; i += stride) {
            int kr = i & 3, r = i >> 2;
            int og = r % 100; r /= 100;
            int j = r & 1; int kg = r >> 1;
            g_W2t[i] = W2[(og * 2 + j) * 400 + kg * 4 + kr];
        }
        for (int i = i0; i < 50 * 2 * 50 * 4; i += stride) {
            int kr = i & 3, r = i >> 2;
            int og = r % 50; r /= 50;
            int j = r & 1; int kg = r >> 1;
            g_W3t[i] = W3[(og * 2 + j) * 200 + kg * 4 + kr];
        }
        for (int i = i0; i < 25 * 10 * 4; i += stride) {
            int kg = i / 40, r = i % 40, o = r >> 2, kr = r & 3;
            g_W4t[i] = W4[o * 100 + kg * 4 + kr];
        }
        return;
    }

    extern __shared__ float sm[];
    float* simg = sm;                          // 5 * 3072 floats (60KB)
    float* spkf = sm + 15360;                  // paired codebook, 128*56 floats (28KB)
    const double2* spk = (const double2*)spkf;

    int p0 = (blockIdx.x - NPREP) * 768;
    int i0 = p0 / 225;
    int total = B * 225;
#pragma unroll
    for (int s = 0; s < 5; s++) {
        int img = i0 + s; if (img > B - 1) img = B - 1;
        const float4* xb = (const float4*)(x + (size_t)img * 3072);
        float4* d = (float4*)(simg + s * 3072);
        for (int i = threadIdx.x; i < 768; i += 256) d[i] = xb[i];
    }
    // self-pack codebook (pair-interleaved): thread c packs code c
    {
        int c = threadIdx.x;
        int q = c >> 1, e = c & 1;
        float nrm = 0.f;
        const float* src = somg + c * 27;
#pragma unroll
        for (int k = 0; k < 27; k++) {
            float v = src[k];
            nrm += v * v;
            spkf[q * 56 + k * 2 + e] = v;
        }
        spkf[q * 56 + 54 + e] = -0.5f * nrm;
    }
    __syncthreads();

    int pA = p0 + threadIdx.x;
    int pB = pA + 256;
    int pC = pA + 512;
    bool wA = pA < total, wB = pB < total, wC = pC < total;
    if (!wA) pA = total - 1;
    if (!wB) pB = pA;
    if (!wC) pC = pB;

    int imgA = pA / 225, tA = pA - imgA * 225;
    int imgB = pB / 225, tB = pB - imgB * 225;
    int imgC = pC / 225, tC = pC - imgC * 225;
    const float* baseA = simg + (imgA - i0) * 3072 + (tA / 15) * 64 + (tA % 15) * 2;
    const float* baseB = simg + (imgB - i0) * 3072 + (tB / 15) * 64 + (tB % 15) * 2;
    const float* baseC = simg + (imgC - i0) * 3072 + (tC / 15) * 64 + (tC % 15) * 2;

    ull pa[27], pb[27], pc[27];
#pragma unroll
    for (int c = 0; c < 3; c++)
#pragma unroll
        for (int i = 0; i < 3; i++)
#pragma unroll
            for (int j = 0; j < 3; j++) {
                int off = c * 1024 + i * 32 + j;
                int idx = c * 9 + i * 3 + j;
                float vA = baseA[off];
                float vB = baseB[off];
                float vC = baseC[off];
                pa[idx] = pack2(vA, vA);
                pb[idx] = pack2(vB, vB);
                pc[idx] = pack2(vC, vC);
            }

    float bestA = -3.4e38f, bestB = -3.4e38f, bestC = -3.4e38f;
    int idxA = 0, idxB = 0, idxC = 0;
#pragma unroll 1
    for (int q = 0; q < 128; q += 2) {
        const double2* P0 = spk + q * 14;
        const double2* P1 = P0 + 14;
        double2 t0 = P0[13], t1 = P1[13];
        ull n0 = (ull)__double_as_longlong(t0.y);
        ull n1 = (ull)__double_as_longlong(t1.y);
        ull c26_0 = (ull)__double_as_longlong(t0.x);
        ull c26_1 = (ull)__double_as_longlong(t1.x);
        ull a0 = ffma2(pa[26], c26_0, n0);
        ull a1 = ffma2(pa[26], c26_1, n1);
        ull b0 = ffma2(pb[26], c26_0, n0);
        ull b1 = ffma2(pb[26], c26_1, n1);
        ull c0 = ffma2(pc[26], c26_0, n0);
        ull c1 = ffma2(pc[26], c26_1, n1);
#pragma unroll
        for (int j = 0; j < 13; j++) {
            double2 v0 = P0[j];
            double2 v1 = P1[j];
            ull w0 = (ull)__double_as_longlong(v0.x);
            ull w1 = (ull)__double_as_longlong(v0.y);
            ull w2 = (ull)__double_as_longlong(v1.x);
            ull w3 = (ull)__double_as_longlong(v1.y);
            a0 = ffma2(pa[2 * j],     w0, a0);
            b0 = ffma2(pb[2 * j],     w0, b0);
            c0 = ffma2(pc[2 * j],     w0, c0);
            a0 = ffma2(pa[2 * j + 1], w1, a0);
            b0 = ffma2(pb[2 * j + 1], w1, b0);
            c0 = ffma2(pc[2 * j + 1], w1, c0);
            a1 = ffma2(pa[2 * j],     w2, a1);
            b1 = ffma2(pb[2 * j],     w2, b1);
            c1 = ffma2(pc[2 * j],     w2, c1);
            a1 = ffma2(pa[2 * j + 1], w3, a1);
            b1 = ffma2(pb[2 * j + 1], w3, b1);
            c1 = ffma2(pc[2 * j + 1], w3, c1);
        }
        float sA0 = lo32(a0), sA1 = hi32(a0), sA2 = lo32(a1), sA3 = hi32(a1);
        if (sA0 > bestA) { bestA = sA0; idxA = 2 * q; }
        if (sA1 > bestA) { bestA = sA1; idxA = 2 * q + 1; }
        if (sA2 > bestA) { bestA = sA2; idxA = 2 * q + 2; }
        if (sA3 > bestA) { bestA = sA3; idxA = 2 * q + 3; }
        float sB0 = lo32(b0), sB1 = hi32(b0), sB2 = lo32(b1), sB3 = hi32(b1);
        if (sB0 > bestB) { bestB = sB0; idxB = 2 * q; }
        if (sB1 > bestB) { bestB = sB1; idxB = 2 * q + 1; }
        if (sB2 > bestB) { bestB = sB2; idxB = 2 * q + 2; }
        if (sB3 > bestB) { bestB = sB3; idxB = 2 * q + 3; }
        float sC0 = lo32(c0), sC1 = hi32(c0), sC2 = lo32(c1), sC3 = hi32(c1);
        if (sC0 > bestC) { bestC = sC0; idxC = 2 * q; }
        if (sC1 > bestC) { bestC = sC1; idxC = 2 * q + 1; }
        if (sC2 > bestC) { bestC = sC2; idxC = 2 * q + 2; }
        if (sC3 > bestC) { bestC = sC3; idxC = 2 * q + 3; }
    }
    if (wA) {
        float* fb = g_feat + (size_t)imgA * 450;
        fb[tA]       = (float)(idxA >> 4) * 0.0625f;
        fb[225 + tA] = (float)(idxA & 15) * 0.0625f;
    }
    if (wB) {
        float* fb = g_feat + (size_t)imgB * 450;
        fb[tB]       = (float)(idxB >> 4) * 0.0625f;
        fb[225 + tB] = (float)(idxB & 15) * 0.0625f;
    }
    if (wC) {
        float* fb = g_feat + (size_t)imgC * 450;
        fb[tC]       = (float)(idxC >> 4) * 0.0625f;
        fb[225 + tC] = (float)(idxC & 15) * 0.0625f;
    }
}

// ---------------- MLP: R11 exact (best measured: 49.7us) ----------------
#define MTHREADS 256
#define NIMG 14
#define WBUF_U2 3200                // L1 chunk: 8 kg x 400 outs (51.2KB)

#define SA_U2 0                     // 120*14 = 1680 u2
#define SB_U2 1680                  // 100*14 = 1400 u2
#define SW_U2 3080
#define SM_U2 (3080 + 2 * WBUF_U2)  // 9480 u2 = 151.7KB

template <int NGK, int CK, int OPT, int NOG, int NOGP, int IMG, bool RELU>
__device__ __forceinline__ void layer(const float* __restrict__ Wg, const float* __restrict__ bias,
                                      const ulonglong2* sin, float* sout,
                                      ulonglong2* wbuf, uint32_t wbuf_s) {
    constexpr int NJG = NIMG / IMG;           // image groups
    constexpr int CEF = CK * OPT * NOG * 4;   // floats per chunk
    constexpr int NCH = NGK / CK;             // exact
    int tid = threadIdx.x;

    for (int i = tid; i < CEF / 4; i += MTHREADS) cp_async16(wbuf_s + i * 16, Wg + i * 4);
    CP_COMMIT(); CP_WAIT0();
    __syncthreads();

    int og = tid % NOGP, jg = tid / NOGP;
    bool active = (og < NOG) && (jg < NJG);
    ull acc[OPT * IMG];
#pragma unroll
    for (int i = 0; i < OPT * IMG; i++) acc[i] = 0;

#pragma unroll 1
    for (int c = 0; c < NCH; c++) {
        const ulonglong2* w = wbuf + (c & 1) * WBUF_U2;
        if (c + 1 < NCH) {
            uint32_t dst = wbuf_s + ((c + 1) & 1) * WBUF_U2 * 16;
            const float* src = Wg + (c + 1) * CEF;
            for (int i = tid; i < CEF / 4; i += MTHREADS) cp_async16(dst + i * 16, src + i * 4);
            CP_COMMIT();
        }
        if (active) {
#pragma unroll
            for (int kk = 0; kk < CK; kk++) {
                ulonglong2 av[IMG], wv[OPT];
#pragma unroll
                for (int i = 0; i < IMG; i++)
                    av[i] = sin[(c * CK + kk) * NIMG + jg * IMG + i];
#pragma unroll
                for (int j = 0; j < OPT; j++)
                    wv[j] = w[(kk * OPT + j) * NOG + og];
#pragma unroll
                for (int j = 0; j < OPT; j++)
#pragma unroll
                    for (int i = 0; i < IMG; i++) {
                        acc[j * IMG + i] = ffma2(av[i].x, wv[j].x, acc[j * IMG + i]);
                        acc[j * IMG + i] = ffma2(av[i].y, wv[j].y, acc[j * IMG + i]);
                    }
            }
        }
        CP_WAIT0();
        __syncthreads();
    }

    if (active) {
#pragma unroll
        for (int j = 0; j < OPT; j++) {
            int o = og * OPT + j;
            float bv = __ldg(bias + o);
#pragma unroll
            for (int i = 0; i < IMG; i++) {
                float v = lo32(acc[j * IMG + i]) + hi32(acc[j * IMG + i]) + bv;
                if (RELU) v = fmaxf(v, 0.f);
                int im = jg * IMG + i;
                sout[((o >> 2) * NIMG + im) * 4 + (o & 3)] = v;
            }
        }
    }
    __syncthreads();
}

__global__ __launch_bounds__(MTHREADS, 1) void mlp_kernel(const float* __restrict__ b1, const float* __restrict__ b2,
                                                          const float* __restrict__ b3, const float* __restrict__ b4,
                                                          float* __restrict__ out, int B) {
    extern __shared__ ulonglong2 smu[];
    ulonglong2* A = smu + SA_U2;
    ulonglong2* Bm = smu + SB_U2;
    ulonglong2* wbuf = smu + SW_U2;
    uint32_t wbuf_s = (uint32_t)__cvta_generic_to_shared(wbuf);
    int tid = threadIdx.x;
    int b0 = blockIdx.x * NIMG;

    // features -> A [kg][img(14)][4], zero-pad k >= 450
    float* Af = (float*)A;
    for (int i = tid; i < 120 * NIMG * 4; i += MTHREADS) {
        int kg = i / (NIMG * 4), r = i % (NIMG * 4), im = r >> 2, kr = r & 3;
        int k = kg * 4 + kr;
        int b = b0 + im; if (b > B - 1) b = B - 1;
        Af[i] = (k < 450) ? g_feat[(size_t)b * 450 + k] : 0.f;
    }
    __syncthreads();

    layer<120, 8, 4, 100, 128, 7, true>(g_W1t, b1, A, (float*)Bm, wbuf, wbuf_s);   // 450->400
    layer<100, 10, 2, 100, 128, 7, true>(g_W2t, b2, Bm, (float*)A, wbuf, wbuf_s);  // 400->200
    layer<50, 10, 2, 50, 64, 7, true>(g_W3t, b3, A, (float*)Bm, wbuf, wbuf_s);     // 200->100

    // final 100 -> 10 (L1-resident __ldg weights)
    for (int job = tid; job < 10 * NIMG; job += MTHREADS) {
        int o = job % 10, im = job / 10;
        const ulonglong2* ar = Bm + im;
        ull acc = 0;
#pragma unroll
        for (int kg = 0; kg < 25; kg++) {
            ulonglong2 wv = __ldg((const ulonglong2*)g_W4t + kg * 10 + o);
            ulonglong2 av = ar[kg * NIMG];
            acc = ffma2(av.x, wv.x, acc);
            acc = ffma2(av.y, wv.y, acc);
        }
        int b = b0 + im;
        if (b < B) out[(size_t)b * 10 + o] = lo32(acc) + hi32(acc) + __ldg(b4 + o);
    }
}

// ---------------- launch ----------------
extern "C" void kernel_launch(void* const* d_in, const int* in_sizes, int n_in,
                              void* d_out, int out_size) {
    const float* x   = (const float*)d_in[0];
    const float* som = (const float*)d_in[1];
    const float* W1  = (const float*)d_in[2];
    const float* b1  = (const float*)d_in[3];
    const float* W2  = (const float*)d_in[4];
    const float* b2  = (const float*)d_in[5];
    const float* W3  = (const float*)d_in[6];
    const float* b3  = (const float*)d_in[7];
    const float* W4  = (const float*)d_in[8];
    const float* b4  = (const float*)d_in[9];
    float* out = (float*)d_out;

    int B = in_sizes[0] / 3072;
    if (B > BMAX) B = BMAX;

    int som_smem = (5 * 3072) * 4 + 128 * 56 * 4;   // 61440 + 28672 = 90112 B
    cudaFuncSetAttribute(som_kernel, cudaFuncAttributeMaxDynamicSharedMemorySize, som_smem);
    cudaFuncSetAttribute(mlp_kernel, cudaFuncAttributeMaxDynamicSharedMemorySize, SM_U2 * 16);

    int total_p = B * 225;
    int nsom = (total_p + 767) / 768;
    som_kernel<<<NPREP + nsom, 256, som_smem>>>(x, som, W1, W2, W3, W4, B);
    mlp_kernel<<<(B + NIMG - 1) / NIMG, MTHREADS, SM_U2 * 16>>>(b1, b2, b3, b4, out, B);
}

// round 14
// speedup vs baseline: 1.1376x; 1.0348x over previous
#include <cuda_runtime.h>
#include <cstdint>

typedef unsigned long long ull;

#define BMAX 2048
#define NPREP 128

// ---------------- device scratch ----------------
__device__ __align__(16) float g_feat[BMAX * 450];    // SOM features [b][450]
// weights interleaved [kg][j][og][4] per-layer (OPT: 4/2/2)
__device__ __align__(16) float g_W1t[120 * 4 * 100 * 4];  // k padded 450->480
__device__ __align__(16) float g_W2t[100 * 2 * 100 * 4];
__device__ __align__(16) float g_W3t[50 * 2 * 50 * 4];
__device__ __align__(16) float g_W4t[25 * 10 * 4];        // [kg][o][4]

// ---------------- f32x2 helpers ----------------
__device__ __forceinline__ ull ffma2(ull a, ull b, ull c) {
    ull d;
    asm("fma.rn.f32x2 %0, %1, %2, %3;" : "=l"(d) : "l"(a), "l"(b), "l"(c));
    return d;
}
__device__ __forceinline__ ull pack2(float lo, float hi) {
    ull r;
    asm("mov.b64 %0, {%1, %2};" : "=l"(r) : "f"(lo), "f"(hi));
    return r;
}
__device__ __forceinline__ float lo32(ull v) { return __uint_as_float((unsigned)v); }
__device__ __forceinline__ float hi32(ull v) { return __uint_as_float((unsigned)(v >> 32)); }

__device__ __forceinline__ void cp_async16(uint32_t saddr, const float* g) {
    asm volatile("cp.async.cg.shared.global [%0], [%1], 16;" :: "r"(saddr), "l"(g));
}
#define CP_COMMIT() asm volatile("cp.async.commit_group;")
#define CP_WAIT0()  asm volatile("cp.async.wait_group 0;")

// ---------------- SOM + weight-prep fused; PREP BLOCKS FIRST (R11 exact) ----------------
__global__ __launch_bounds__(256, 1) void som_kernel(const float* __restrict__ x,
                                                     const float* __restrict__ somg,
                                                     const float* __restrict__ W1, const float* __restrict__ W2,
                                                     const float* __restrict__ W3, const float* __restrict__ W4,
                                                     int B) {
    if (blockIdx.x < NPREP) {
        int i0 = blockIdx.x * 256 + threadIdx.x;
        int stride = NPREP * 256;
        for (int i = i0; i < 120 * 4 * 100 * 4; i += stride) {
            int kr = i & 3, r = i >> 2;
            int og = r % 100; r /= 100;
            int j = r & 3; int kg = r >> 2;
            int k = kg * 4 + kr, o = og * 4 + j;
            g_W1t[i] = (k < 450) ? W1[o * 450 + k] : 0.f;
        }
        for (int i = i0; i < 100 * 2 * 100 * 4; i += stride) {
            int kr = i & 3, r = i >> 2;
            int og = r % 100; r /= 100;
            int j = r & 1; int kg = r >> 1;
            g_W2t[i] = W2[(og * 2 + j) * 400 + kg * 4 + kr];
        }
        for (int i = i0; i < 50 * 2 * 50 * 4; i += stride) {
            int kr = i & 3, r = i >> 2;
            int og = r % 50; r /= 50;
            int j = r & 1; int kg = r >> 1;
            g_W3t[i] = W3[(og * 2 + j) * 200 + kg * 4 + kr];
        }
        for (int i = i0; i < 25 * 10 * 4; i += stride) {
            int kg = i / 40, r = i % 40, o = r >> 2, kr = r & 3;
            g_W4t[i] = W4[o * 100 + kg * 4 + kr];
        }
        return;
    }

    extern __shared__ float sm[];
    float* simg = sm;                          // 4 * 3072 floats
    float* spkf = sm + 12288;                  // paired codebook, 128*56 floats
    const double2* spk = (const double2*)spkf;

    int p0 = (blockIdx.x - NPREP) * 512;
    int i0 = p0 / 225;
    int total = B * 225;
#pragma unroll
    for (int s = 0; s < 4; s++) {
        int img = i0 + s; if (img > B - 1) img = B - 1;
        const float4* xb = (const float4*)(x + (size_t)img * 3072);
        float4* d = (float4*)(simg + s * 3072);
        for (int i = threadIdx.x; i < 768; i += 256) d[i] = xb[i];
    }
    {
        int c = threadIdx.x;
        int q = c >> 1, e = c & 1;
        float nrm = 0.f;
        const float* src = somg + c * 27;
#pragma unroll
        for (int k = 0; k < 27; k++) {
            float v = src[k];
            nrm += v * v;
            spkf[q * 56 + k * 2 + e] = v;
        }
        spkf[q * 56 + 54 + e] = -0.5f * nrm;
    }
    __syncthreads();

    int pA = p0 + threadIdx.x;
    int pB = pA + 256;
    bool wA = pA < total, wB = pB < total;
    if (!wA) pA = total - 1;
    if (!wB) pB = pA;

    int imgA = pA / 225, tA = pA - imgA * 225;
    int imgB = pB / 225, tB = pB - imgB * 225;
    const float* baseA = simg + (imgA - i0) * 3072 + (tA / 15) * 64 + (tA % 15) * 2;
    const float* baseB = simg + (imgB - i0) * 3072 + (tB / 15) * 64 + (tB % 15) * 2;

    ull pa[27], pb[27];
#pragma unroll
    for (int c = 0; c < 3; c++)
#pragma unroll
        for (int i = 0; i < 3; i++)
#pragma unroll
            for (int j = 0; j < 3; j++) {
                float vA = baseA[c * 1024 + i * 32 + j];
                float vB = baseB[c * 1024 + i * 32 + j];
                pa[c * 9 + i * 3 + j] = pack2(vA, vA);
                pb[c * 9 + i * 3 + j] = pack2(vB, vB);
            }

    float bestA = -3.4e38f, bestB = -3.4e38f;
    int idxA = 0, idxB = 0;
#pragma unroll 2
    for (int q = 0; q < 128; q += 2) {
        const double2* P0 = spk + q * 14;
        const double2* P1 = P0 + 14;
        double2 t0 = P0[13], t1 = P1[13];
        ull n0 = (ull)__double_as_longlong(t0.y);
        ull n1 = (ull)__double_as_longlong(t1.y);
        ull c26_0 = (ull)__double_as_longlong(t0.x);
        ull c26_1 = (ull)__double_as_longlong(t1.x);
        ull a0 = ffma2(pa[26], c26_0, n0);
        ull a1 = ffma2(pa[26], c26_1, n1);
        ull b0 = ffma2(pb[26], c26_0, n0);
        ull b1 = ffma2(pb[26], c26_1, n1);
#pragma unroll
        for (int j = 0; j < 13; j++) {
            double2 v0 = P0[j];
            double2 v1 = P1[j];
            ull w0 = (ull)__double_as_longlong(v0.x);
            ull w1 = (ull)__double_as_longlong(v0.y);
            ull w2 = (ull)__double_as_longlong(v1.x);
            ull w3 = (ull)__double_as_longlong(v1.y);
            a0 = ffma2(pa[2 * j],     w0, a0);
            b0 = ffma2(pb[2 * j],     w0, b0);
            a0 = ffma2(pa[2 * j + 1], w1, a0);
            b0 = ffma2(pb[2 * j + 1], w1, b0);
            a1 = ffma2(pa[2 * j],     w2, a1);
            b1 = ffma2(pb[2 * j],     w2, b1);
            a1 = ffma2(pa[2 * j + 1], w3, a1);
            b1 = ffma2(pb[2 * j + 1], w3, b1);
        }
        float sA0 = lo32(a0), sA1 = hi32(a0), sA2 = lo32(a1), sA3 = hi32(a1);
        if (sA0 > bestA) { bestA = sA0; idxA = 2 * q; }
        if (sA1 > bestA) { bestA = sA1; idxA = 2 * q + 1; }
        if (sA2 > bestA) { bestA = sA2; idxA = 2 * q + 2; }
        if (sA3 > bestA) { bestA = sA3; idxA = 2 * q + 3; }
        float sB0 = lo32(b0), sB1 = hi32(b0), sB2 = lo32(b1), sB3 = hi32(b1);
        if (sB0 > bestB) { bestB = sB0; idxB = 2 * q; }
        if (sB1 > bestB) { bestB = sB1; idxB = 2 * q + 1; }
        if (sB2 > bestB) { bestB = sB2; idxB = 2 * q + 2; }
        if (sB3 > bestB) { bestB = sB3; idxB = 2 * q + 3; }
    }
    if (wA) {
        float* fb = g_feat + (size_t)imgA * 450;
        fb[tA]       = (float)(idxA >> 4) * 0.0625f;
        fb[225 + tA] = (float)(idxA & 15) * 0.0625f;
    }
    if (wB) {
        float* fb = g_feat + (size_t)imgB * 450;
        fb[tB]       = (float)(idxB >> 4) * 0.0625f;
        fb[225 + tB] = (float)(idxB & 15) * 0.0625f;
    }
}

// ---------------- MLP: R11 structure, LANE-PAIRED job mapping (no padding waste) ----------------
// og = tid >> 1 (lane pairs share an output group), jg = tid & 1.
// Active = tid < 2*NOG: warps fully active or fully idle (except one partial).
#define MTHREADS 256
#define NIMG 14
#define WBUF_U2 3200                // L1 chunk: 8 kg x 400 outs (51.2KB)

#define SA_U2 0                     // 120*14 = 1680 u2
#define SB_U2 1680                  // 100*14 = 1400 u2
#define SW_U2 3080
#define SM_U2 (3080 + 2 * WBUF_U2)  // 9480 u2 = 151.7KB

template <int NGK, int CK, int OPT, int NOG, int IMG, bool RELU>
__device__ __forceinline__ void layer(const float* __restrict__ Wg, const float* __restrict__ bias,
                                      const ulonglong2* sin, float* sout,
                                      ulonglong2* wbuf, uint32_t wbuf_s) {
    constexpr int CEF = CK * OPT * NOG * 4;   // floats per chunk
    constexpr int NCH = NGK / CK;             // exact
    int tid = threadIdx.x;

    for (int i = tid; i < CEF / 4; i += MTHREADS) cp_async16(wbuf_s + i * 16, Wg + i * 4);
    CP_COMMIT(); CP_WAIT0();
    __syncthreads();

    int og = tid >> 1, jg = tid & 1;          // lane-paired mapping
    bool active = og < NOG;                   // NJG == 2 always (IMG=7, NIMG=14)
    ull acc[OPT * IMG];
#pragma unroll
    for (int i = 0; i < OPT * IMG; i++) acc[i] = 0;

#pragma unroll 1
    for (int c = 0; c < NCH; c++) {
        const ulonglong2* w = wbuf + (c & 1) * WBUF_U2;
        if (c + 1 < NCH) {
            uint32_t dst = wbuf_s + ((c + 1) & 1) * WBUF_U2 * 16;
            const float* src = Wg + (c + 1) * CEF;
            for (int i = tid; i < CEF / 4; i += MTHREADS) cp_async16(dst + i * 16, src + i * 4);
            CP_COMMIT();
        }
        if (active) {
#pragma unroll
            for (int kk = 0; kk < CK; kk++) {
                ulonglong2 av[IMG], wv[OPT];
#pragma unroll
                for (int i = 0; i < IMG; i++)
                    av[i] = sin[(c * CK + kk) * NIMG + jg * IMG + i];
#pragma unroll
                for (int j = 0; j < OPT; j++)
                    wv[j] = w[(kk * OPT + j) * NOG + og];
#pragma unroll
                for (int j = 0; j < OPT; j++)
#pragma unroll
                    for (int i = 0; i < IMG; i++) {
                        acc[j * IMG + i] = ffma2(av[i].x, wv[j].x, acc[j * IMG + i]);
                        acc[j * IMG + i] = ffma2(av[i].y, wv[j].y, acc[j * IMG + i]);
                    }
            }
        }
        CP_WAIT0();
        __syncthreads();
    }

    if (active) {
#pragma unroll
        for (int j = 0; j < OPT; j++) {
            int o = og * OPT + j;
            float bv = __ldg(bias + o);
#pragma unroll
            for (int i = 0; i < IMG; i++) {
                float v = lo32(acc[j * IMG + i]) + hi32(acc[j * IMG + i]) + bv;
                if (RELU) v = fmaxf(v, 0.f);
                int im = jg * IMG + i;
                sout[((o >> 2) * NIMG + im) * 4 + (o & 3)] = v;
            }
        }
    }
    __syncthreads();
}

__global__ __launch_bounds__(MTHREADS, 1) void mlp_kernel(const float* __restrict__ b1, const float* __restrict__ b2,
                                                          const float* __restrict__ b3, const float* __restrict__ b4,
                                                          float* __restrict__ out, int B) {
    extern __shared__ ulonglong2 smu[];
    ulonglong2* A = smu + SA_U2;
    ulonglong2* Bm = smu + SB_U2;
    ulonglong2* wbuf = smu + SW_U2;
    uint32_t wbuf_s = (uint32_t)__cvta_generic_to_shared(wbuf);
    int tid = threadIdx.x;
    int b0 = blockIdx.x * NIMG;

    // features -> A [kg][img(14)][4], zero-pad k >= 450
    float* Af = (float*)A;
    for (int i = tid; i < 120 * NIMG * 4; i += MTHREADS) {
        int kg = i / (NIMG * 4), r = i % (NIMG * 4), im = r >> 2, kr = r & 3;
        int k = kg * 4 + kr;
        int b = b0 + im; if (b > B - 1) b = B - 1;
        Af[i] = (k < 450) ? g_feat[(size_t)b * 450 + k] : 0.f;
    }
    __syncthreads();

    layer<120, 8, 4, 100, 7, true>(g_W1t, b1, A, (float*)Bm, wbuf, wbuf_s);   // 450->400
    layer<100, 10, 2, 100, 7, true>(g_W2t, b2, Bm, (float*)A, wbuf, wbuf_s);  // 400->200
    layer<50, 10, 2, 50, 7, true>(g_W3t, b3, A, (float*)Bm, wbuf, wbuf_s);    // 200->100

    // final 100 -> 10 (L1-resident __ldg weights)
    for (int job = tid; job < 10 * NIMG; job += MTHREADS) {
        int o = job % 10, im = job / 10;
        const ulonglong2* ar = Bm + im;
        ull acc = 0;
#pragma unroll
        for (int kg = 0; kg < 25; kg++) {
            ulonglong2 wv = __ldg((const ulonglong2*)g_W4t + kg * 10 + o);
            ulonglong2 av = ar[kg * NIMG];
            acc = ffma2(av.x, wv.x, acc);
            acc = ffma2(av.y, wv.y, acc);
        }
        int b = b0 + im;
        if (b < B) out[(size_t)b * 10 + o] = lo32(acc) + hi32(acc) + __ldg(b4 + o);
    }
}

// ---------------- launch ----------------
extern "C" void kernel_launch(void* const* d_in, const int* in_sizes, int n_in,
                              void* d_out, int out_size) {
    const float* x   = (const float*)d_in[0];
    const float* som = (const float*)d_in[1];
    const float* W1  = (const float*)d_in[2];
    const float* b1  = (const float*)d_in[3];
    const float* W2  = (const float*)d_in[4];
    const float* b2  = (const float*)d_in[5];
    const float* W3  = (const float*)d_in[6];
    const float* b3  = (const float*)d_in[7];
    const float* W4  = (const float*)d_in[8];
    const float* b4  = (const float*)d_in[9];
    float* out = (float*)d_out;

    int B = in_sizes[0] / 3072;
    if (B > BMAX) B = BMAX;

    int som_smem = (4 * 3072) * 4 + 128 * 56 * 4;   // 77824 B
    cudaFuncSetAttribute(som_kernel, cudaFuncAttributeMaxDynamicSharedMemorySize, som_smem);
    cudaFuncSetAttribute(mlp_kernel, cudaFuncAttributeMaxDynamicSharedMemorySize, SM_U2 * 16);

    int total_p = B * 225;
    int nsom = (total_p + 511) / 512;
    som_kernel<<<NPREP + nsom, 256, som_smem>>>(x, som, W1, W2, W3, W4, B);
    mlp_kernel<<<(B + NIMG - 1) / NIMG, MTHREADS, SM_U2 * 16>>>(b1, b2, b3, b4, out, B);
}